// round 15
// baseline (speedup 1.0000x reference)
#include <cuda_runtime.h>
#include <cuda_fp16.h>
#include <math.h>

#define NN      100000
#define EE      1600000
#define DIN_    128
#define HID_    64
#define DOUT_   40
#define NLAYERS 8
#define NB1     ((NN + 511) / 512)   // 196 scan blocks

// ---------------- scratch (device globals; no allocation allowed) ----------
__device__ int    g_degi[NN];
__device__ float  g_dinv[NN];
__device__ int    g_off[NN + 1];    // +1: sentinel g_off[NN] = EE
__device__ int    g_cur[NN];
__device__ int    g_bsum[256];
__device__ int    g_boff[256];
__device__ uint2  g_edge[EE];       // {src, __float_as_uint(0.9*w)}
__device__ int    g_edst[EE];       // dst per CSR slot
__device__ uint4  g_h0h[NN * 8];    // fp16 h: 64 halves/row = 8 uint4
__device__ uint4  g_hah[NN * 8];
__device__ uint4  g_hbh[NN * 8];
__device__ __half g_Mh[NLAYERS * HID_ * HID_];
__device__ __half g_W1h[DIN_ * HID_];

// ---------------- helpers ---------------------------------------------------
__device__ __forceinline__ void fma8(float* acc, uint4 u, float w) {
    float2 p;
    p = __half22float2(*(__half2*)&u.x); acc[0] += w * p.x; acc[1] += w * p.y;
    p = __half22float2(*(__half2*)&u.y); acc[2] += w * p.x; acc[3] += w * p.y;
    p = __half22float2(*(__half2*)&u.z); acc[4] += w * p.x; acc[5] += w * p.y;
    p = __half22float2(*(__half2*)&u.w); acc[6] += w * p.x; acc[7] += w * p.y;
}

__device__ __forceinline__ void ldsm_x4(unsigned* r, unsigned addr) {
    asm volatile("ldmatrix.sync.aligned.m8n8.x4.shared.b16 {%0,%1,%2,%3}, [%4];"
                 : "=r"(r[0]), "=r"(r[1]), "=r"(r[2]), "=r"(r[3]) : "r"(addr));
}
__device__ __forceinline__ void ldsm_x4_t(unsigned* r, unsigned addr) {
    asm volatile("ldmatrix.sync.aligned.m8n8.x4.trans.shared.b16 {%0,%1,%2,%3}, [%4];"
                 : "=r"(r[0]), "=r"(r[1]), "=r"(r[2]), "=r"(r[3]) : "r"(addr));
}
__device__ __forceinline__ void mma_f16(float* d, const unsigned* a, const unsigned* b) {
    asm volatile(
        "mma.sync.aligned.m16n8k16.row.col.f32.f16.f16.f32 "
        "{%0,%1,%2,%3}, {%4,%5,%6,%7}, {%8,%9}, {%0,%1,%2,%3};"
        : "+f"(d[0]), "+f"(d[1]), "+f"(d[2]), "+f"(d[3])
        : "r"(a[0]), "r"(a[1]), "r"(a[2]), "r"(a[3]), "r"(b[0]), "r"(b[1]));
}

__device__ __forceinline__ void flush_af(float* Af, int cur, int j, float* acc) {
    if (cur >= 0) {
        float* p = Af + cur * 68 + j * 8;
#pragma unroll
        for (int i = 0; i < 8; i++) { atomicAdd(p + i, acc[i]); acc[i] = 0.f; }
    }
}

// ---------------- graph prep (edge_index is INT32) -------------------------
__global__ void deg_zero_k() {
    int i = blockIdx.x * blockDim.x + threadIdx.x;
    if (i < NN) g_degi[i] = 0;
}

__global__ void deg_count_k(const int* __restrict__ ei) {
    int e = blockIdx.x * blockDim.x + threadIdx.x;
    if (e < EE) {
        int d = ei[EE + e];
        if (d >= 0 && d < NN) atomicAdd(&g_degi[d], 1);
    }
}

// scan1 also computes dinv (reads g_degi anyway)
__global__ void scan1_k() {
    __shared__ int s[1024];
    int t = threadIdx.x;
    int i = blockIdx.x * 512 + t;
    int v = (i < NN) ? g_degi[i] : 0;
    if (i < NN) g_dinv[i] = rsqrtf((float)v + 1.0f);   // +1 self-loop
    s[t] = 0;
    s[512 + t] = v;
    __syncthreads();
#pragma unroll
    for (int d = 1; d < 512; d <<= 1) {
        int u = s[512 + t - d];
        __syncthreads();
        s[512 + t] += u;
        __syncthreads();
    }
    if (i < NN) g_off[i] = s[512 + t] - v;
    if (t == 511) g_bsum[blockIdx.x] = s[512 + 511];
}

__global__ void scan2_k() {
    __shared__ int s[512];
    int t = threadIdx.x;
    int v = (t < NB1) ? g_bsum[t] : 0;
    s[t] = 0;
    s[256 + t] = v;
    __syncthreads();
#pragma unroll
    for (int d = 1; d < 256; d <<= 1) {
        int u = s[256 + t - d];
        __syncthreads();
        s[256 + t] += u;
        __syncthreads();
    }
    g_boff[t] = s[256 + t] - v;
}

__global__ void scan3_k() {
    int i = blockIdx.x * 512 + threadIdx.x;
    if (i < NN) {
        int o = g_off[i] + g_boff[blockIdx.x];
        g_off[i] = o;
        g_cur[i] = o;
        if (i == NN - 1) g_off[NN] = o + g_degi[i];   // sentinel
    }
}

__global__ void fill_k(const int* __restrict__ ei) {
    int e = blockIdx.x * blockDim.x + threadIdx.x;
    if (e < EE) {
        int s = ei[e];
        int d = ei[EE + e];
        if (s >= 0 && s < NN && d >= 0 && d < NN) {
            int pos = atomicAdd(&g_cur[d], 1);
            uint2 pe;
            pe.x = (unsigned)s;
            pe.y = __float_as_uint(0.9f * g_dinv[s] * g_dinv[d]);
            g_edge[pos] = pe;
            g_edst[pos] = d;
        }
    }
}

// merged: M_l = (1-beta)*I + beta*W_l (fp16) AND W1 -> fp16
__global__ void weights_k(const float* __restrict__ cw, const float* __restrict__ W1) {
    int idx = blockIdx.x * blockDim.x + threadIdx.x;
    if (idx < NLAYERS * HID_ * HID_) {
        int l = idx >> 12;
        int rc = idx & 4095;
        int r = rc >> 6, c = rc & 63;
        float beta = logf(0.5f / (float)(l + 1) + 1.0f);
        float v = beta * cw[idx];
        if (r == c) v += 1.0f - beta;
        g_Mh[idx] = __float2half(v);
    } else if (idx < NLAYERS * HID_ * HID_ + DIN_ * HID_) {
        int k = idx - NLAYERS * HID_ * HID_;
        g_W1h[k] = __float2half(W1[k]);
    }
}

// ---------------- fused layer: edge-balanced gather + HMMA + relu ----------
// 256 threads = 32 groups x 8 lanes. Block owns rows [row0, row0+64) and the
// contiguous CSR edge range; each group handles an equal chunk of edges.
__global__ void __launch_bounds__(256) layer_k(int layer) {
    __shared__ __align__(16) float  Af[64 * 68];   // fp32 accum tile
    __shared__ __align__(16) __half Ah[64 * 72];   // fp16 A for ldmatrix
    __shared__ __align__(16) __half Bh[64 * 72];

    const uint4* __restrict__ hin =
        (layer == 0) ? g_h0h : ((layer & 1) ? g_hah : g_hbh);
    uint4* __restrict__ hout = (layer & 1) ? g_hbh : g_hah;

    int tid = threadIdx.x;
    int row0 = blockIdx.x << 6;

    // load M_l (fp16) into Bh with padded stride
    {
        const unsigned* Mw = (const unsigned*)(g_Mh + layer * 4096);  // 2048 words
        unsigned* Bw = (unsigned*)Bh;
#pragma unroll
        for (int t = 0; t < 8; t++) {
            int v = t * 256 + tid;
            Bw[(v >> 5) * 36 + (v & 31)] = Mw[v];
        }
    }

    // ---- init Af with self-loop + 0.1*h0 (also zeroes padding rows) ----
#pragma unroll
    for (int t = 0; t < 2; t++) {
        int slice = tid + t * 256;        // 0..511
        int r = slice >> 3, jj = slice & 7;
        int row = row0 + r;
        float a[8] = {0.f, 0.f, 0.f, 0.f, 0.f, 0.f, 0.f, 0.f};
        if (row < NN) {
            float di = g_dinv[row];
            fma8(a, hin[row * 8 + jj], 0.9f * di * di);
            fma8(a, g_h0h[row * 8 + jj], 0.1f);
        }
        float* p = Af + r * 68 + jj * 8;
        *(float4*)p = make_float4(a[0], a[1], a[2], a[3]);
        *(float4*)(p + 4) = make_float4(a[4], a[5], a[6], a[7]);
    }
    __syncthreads();

    // ---- edge phase: equal chunks per group, register accum, flush on row change
    {
        int group = tid >> 3, j = tid & 7;
        int e0 = g_off[row0];
        int rend = row0 + 64; if (rend > NN) rend = NN;
        int e1 = g_off[rend];
        int ne = e1 - e0;
        int chunk = (ne + 31) >> 5;
        int gs = e0 + group * chunk;
        int ge = gs + chunk; if (ge > e1) ge = e1;

        float acc[8] = {0.f, 0.f, 0.f, 0.f, 0.f, 0.f, 0.f, 0.f};
        int cur = -1;
        int e = gs;
        for (; e + 3 < ge; e += 4) {
            uint2 q0 = g_edge[e],     q1 = g_edge[e + 1];
            uint2 q2 = g_edge[e + 2], q3 = g_edge[e + 3];
            int r0 = g_edst[e]     - row0;
            int r1 = g_edst[e + 1] - row0;
            int r2 = g_edst[e + 2] - row0;
            int r3 = g_edst[e + 3] - row0;
            uint4 v0 = hin[q0.x * 8 + j];
            uint4 v1 = hin[q1.x * 8 + j];
            uint4 v2 = hin[q2.x * 8 + j];
            uint4 v3 = hin[q3.x * 8 + j];
            if (r0 != cur) { flush_af(Af, cur, j, acc); cur = r0; }
            fma8(acc, v0, __uint_as_float(q0.y));
            if (r1 != cur) { flush_af(Af, cur, j, acc); cur = r1; }
            fma8(acc, v1, __uint_as_float(q1.y));
            if (r2 != cur) { flush_af(Af, cur, j, acc); cur = r2; }
            fma8(acc, v2, __uint_as_float(q2.y));
            if (r3 != cur) { flush_af(Af, cur, j, acc); cur = r3; }
            fma8(acc, v3, __uint_as_float(q3.y));
        }
        for (; e < ge; e++) {
            uint2 q0 = g_edge[e];
            int r0 = g_edst[e] - row0;
            uint4 v0 = hin[q0.x * 8 + j];
            if (r0 != cur) { flush_af(Af, cur, j, acc); cur = r0; }
            fma8(acc, v0, __uint_as_float(q0.y));
        }
        flush_af(Af, cur, j, acc);
    }
    __syncthreads();

    // ---- convert Af (fp32) -> Ah (fp16) ----
#pragma unroll
    for (int t = 0; t < 2; t++) {
        int slice = tid + t * 256;
        int r = slice >> 3, jj = slice & 7;
        const float* p = Af + r * 68 + jj * 8;
        float4 f0 = *(const float4*)p;
        float4 f1 = *(const float4*)(p + 4);
        __half2 a = __floats2half2_rn(f0.x, f0.y);
        __half2 b = __floats2half2_rn(f0.z, f0.w);
        __half2 c = __floats2half2_rn(f1.x, f1.y);
        __half2 d = __floats2half2_rn(f1.z, f1.w);
        uint4 st;
        st.x = *(unsigned*)&a; st.y = *(unsigned*)&b;
        st.z = *(unsigned*)&c; st.w = *(unsigned*)&d;
        *(uint4*)(Ah + r * 72 + jj * 8) = st;
    }
    __syncthreads();

    // ---- HMMA: 8 warps, each 16x32 tile ----
    int w = tid >> 5, lane = tid & 31;
    int r0 = (w & 3) * 16;
    int n0 = (w >> 2) * 32;
    float d0[4] = {}, d1[4] = {}, d2[4] = {}, d3[4] = {};

    unsigned Asm = (unsigned)__cvta_generic_to_shared(Ah);
    unsigned Bsm = (unsigned)__cvta_generic_to_shared(Bh);
    int lr = lane & 15, lh = lane >> 4;
#pragma unroll
    for (int ks = 0; ks < 4; ks++) {
        int kk = ks * 16;
        unsigned a[4], b0[4], b1[4];
        ldsm_x4(a, Asm + ((r0 + lr) * 72 + kk + lh * 8) * 2);
        unsigned bad = Bsm + ((kk + lr) * 72 + n0 + lh * 8) * 2;
        ldsm_x4_t(b0, bad);
        ldsm_x4_t(b1, bad + 32);
        mma_f16(d0, a, b0 + 0);
        mma_f16(d1, a, b0 + 2);
        mma_f16(d2, a, b1 + 0);
        mma_f16(d3, a, b1 + 2);
    }

    // epilogue: relu, pack fp16, store
    int tg = lane >> 2, ti = lane & 3;
    unsigned* ho = (unsigned*)hout;   // 32 words per row
    int grow0 = row0 + r0 + tg;
    int grow1 = grow0 + 8;
    float* dd[4] = {d0, d1, d2, d3};
#pragma unroll
    for (int t = 0; t < 4; t++) {
        int col = n0 + t * 8 + ti * 2;
        __half2 lo = __floats2half2_rn(fmaxf(dd[t][0], 0.f), fmaxf(dd[t][1], 0.f));
        __half2 hi = __floats2half2_rn(fmaxf(dd[t][2], 0.f), fmaxf(dd[t][3], 0.f));
        if (grow0 < NN) ho[grow0 * 32 + (col >> 1)] = *(unsigned*)&lo;
        if (grow1 < NN) ho[grow1 * 32 + (col >> 1)] = *(unsigned*)&hi;
    }
}

// ---------------- GEMM1: h0 = relu(x @ W1 + b1), HMMA, K=128 ---------------
__global__ void __launch_bounds__(256) gemm1_k(
    const float* __restrict__ x, const float* __restrict__ bias)
{
    __shared__ __align__(16) __half Ah[64 * 72];
    __shared__ __align__(16) __half Bh[64 * 72];
    __shared__ float bsh[64];

    int tid = threadIdx.x;
    int row0 = blockIdx.x << 6;
    if (tid < 64) bsh[tid] = bias[tid];

    int w = tid >> 5, lane = tid & 31;
    int r0 = (w & 3) * 16;
    int n0 = (w >> 2) * 32;
    int lr = lane & 15, lh = lane >> 4;
    float d0[4] = {}, d1[4] = {}, d2[4] = {}, d3[4] = {};

    unsigned Asm = (unsigned)__cvta_generic_to_shared(Ah);
    unsigned Bsm = (unsigned)__cvta_generic_to_shared(Bh);

#pragma unroll
    for (int kc = 0; kc < 128; kc += 64) {
        {
            const unsigned* Ww = (const unsigned*)(g_W1h + kc * 64);
            unsigned* Bw = (unsigned*)Bh;
#pragma unroll
            for (int t = 0; t < 8; t++) {
                int v = t * 256 + tid;
                Bw[(v >> 5) * 36 + (v & 31)] = Ww[v];
            }
        }
        {
            int r = tid >> 2, q = tid & 3;
            int grow = row0 + r;
            float4 f0 = make_float4(0, 0, 0, 0), f1 = f0, f2 = f0, f3 = f0;
            if (grow < NN) {
                const float4* xr = (const float4*)x + grow * 32 + (kc >> 2) + q * 4;
                f0 = xr[0]; f1 = xr[1]; f2 = xr[2]; f3 = xr[3];
            }
            __half2 h0_ = __floats2half2_rn(f0.x, f0.y);
            __half2 h1_ = __floats2half2_rn(f0.z, f0.w);
            __half2 h2_ = __floats2half2_rn(f1.x, f1.y);
            __half2 h3_ = __floats2half2_rn(f1.z, f1.w);
            __half2 h4_ = __floats2half2_rn(f2.x, f2.y);
            __half2 h5_ = __floats2half2_rn(f2.z, f2.w);
            __half2 h6_ = __floats2half2_rn(f3.x, f3.y);
            __half2 h7_ = __floats2half2_rn(f3.z, f3.w);
            uint4 s0, s1;
            s0.x = *(unsigned*)&h0_; s0.y = *(unsigned*)&h1_;
            s0.z = *(unsigned*)&h2_; s0.w = *(unsigned*)&h3_;
            s1.x = *(unsigned*)&h4_; s1.y = *(unsigned*)&h5_;
            s1.z = *(unsigned*)&h6_; s1.w = *(unsigned*)&h7_;
            *(uint4*)(Ah + r * 72 + q * 16) = s0;
            *(uint4*)(Ah + r * 72 + q * 16 + 8) = s1;
        }
        __syncthreads();

#pragma unroll
        for (int ks = 0; ks < 4; ks++) {
            int kk = ks * 16;
            unsigned a[4], b0[4], b1[4];
            ldsm_x4(a, Asm + ((r0 + lr) * 72 + kk + lh * 8) * 2);
            unsigned bad = Bsm + ((kk + lr) * 72 + n0 + lh * 8) * 2;
            ldsm_x4_t(b0, bad);
            ldsm_x4_t(b1, bad + 32);
            mma_f16(d0, a, b0 + 0);
            mma_f16(d1, a, b0 + 2);
            mma_f16(d2, a, b1 + 0);
            mma_f16(d3, a, b1 + 2);
        }
        __syncthreads();
    }

    int tg = lane >> 2, ti = lane & 3;
    unsigned* ho = (unsigned*)g_h0h;
    int grow0 = row0 + r0 + tg;
    int grow1 = grow0 + 8;
    float* dd[4] = {d0, d1, d2, d3};
#pragma unroll
    for (int t = 0; t < 4; t++) {
        int col = n0 + t * 8 + ti * 2;
        float bx = bsh[col], by = bsh[col + 1];
        __half2 lo = __floats2half2_rn(fmaxf(dd[t][0] + bx, 0.f), fmaxf(dd[t][1] + by, 0.f));
        __half2 hi = __floats2half2_rn(fmaxf(dd[t][2] + bx, 0.f), fmaxf(dd[t][3] + by, 0.f));
        if (grow0 < NN) ho[grow0 * 32 + (col >> 1)] = *(unsigned*)&lo;
        if (grow1 < NN) ho[grow1 * 32 + (col >> 1)] = *(unsigned*)&hi;
    }
}

// ---------------- final GEMM: out = h @ W2 + b2  ([N,64]@[64,40]) ----------
__device__ __forceinline__ float4 u2f4(uint2 u) {
    __half2 a = *(__half2*)&u.x;
    __half2 b = *(__half2*)&u.y;
    float2 fa = __half22float2(a), fb = __half22float2(b);
    return make_float4(fa.x, fa.y, fb.x, fb.y);
}

__global__ void __launch_bounds__(256) final_k(
    const float* __restrict__ W2, const float* __restrict__ b2,
    float* __restrict__ out)
{
    __shared__ float W2s[64 * 40];
    __shared__ float b2s[40];
    int tid = threadIdx.x;
    for (int i = tid; i < 64 * 40; i += 256) W2s[i] = W2[i];
    if (tid < 40) b2s[tid] = b2[tid];
    __syncthreads();

    int row = blockIdx.x * 256 + tid;
    if (row >= NN) return;

    float acc[40];
#pragma unroll
    for (int j = 0; j < 40; j++) acc[j] = b2s[j];

    // last layer is 7 (odd) -> wrote g_hbh
    const uint4* hr = g_hbh + row * 8;
#pragma unroll
    for (int q = 0; q < 8; q++) {
        uint4 u = hr[q];
        float4 f0 = u2f4(make_uint2(u.x, u.y));
        float4 f1 = u2f4(make_uint2(u.z, u.w));
        float hs[8] = {f0.x, f0.y, f0.z, f0.w, f1.x, f1.y, f1.z, f1.w};
#pragma unroll
        for (int kk = 0; kk < 8; kk++) {
            const float* wrow = &W2s[(q * 8 + kk) * 40];
#pragma unroll
            for (int jj = 0; jj < 40; jj++)
                acc[jj] += hs[kk] * wrow[jj];
        }
    }
#pragma unroll
    for (int jj = 0; jj < 40; jj++)
        out[row * 40 + jj] = acc[jj];
}

// ---------------- launch ---------------------------------------------------
extern "C" void kernel_launch(void* const* d_in, const int* in_sizes, int n_in,
                              void* d_out, int out_size) {
    const float* x  = (const float*)d_in[0];
    const int*   ei = (const int*)d_in[1];     // int32 (jax default, no x64)
    const float* W1 = (const float*)d_in[2];
    const float* b1 = (const float*)d_in[3];
    const float* cw = (const float*)d_in[4];
    const float* W2 = (const float*)d_in[5];
    const float* b2 = (const float*)d_in[6];
    float*       out = (float*)d_out;

    deg_zero_k<<<(NN + 255) / 256, 256>>>();
    deg_count_k<<<(EE + 255) / 256, 256>>>(ei);
    scan1_k<<<NB1, 512>>>();
    scan2_k<<<1, 256>>>();
    scan3_k<<<NB1, 512>>>();
    fill_k<<<(EE + 255) / 256, 256>>>(ei);
    weights_k<<<(NLAYERS * HID_ * HID_ + DIN_ * HID_ + 255) / 256, 256>>>(cw, W1);

    gemm1_k<<<(NN + 63) / 64, 256>>>(x, b1);

    for (int l = 0; l < NLAYERS; l++)
        layer_k<<<(NN + 63) / 64, 256>>>(l);

    final_k<<<(NN + 255) / 256, 256>>>(W2, b2, out);
}

// round 16
// speedup vs baseline: 1.5409x; 1.5409x over previous
#include <cuda_runtime.h>
#include <cuda_fp16.h>
#include <math.h>

#define NN      100000
#define EE      1600000
#define DIN_    128
#define HID_    64
#define DOUT_   40
#define NLAYERS 8
#define NB1     ((NN + 511) / 512)   // 196 scan blocks

// ---------------- scratch (device globals; no allocation allowed) ----------
__device__ int    g_degi[NN];
__device__ float  g_dinv[NN];
__device__ int    g_off[NN + 1];
__device__ int    g_cur[NN];
__device__ int    g_bsum[256];
__device__ int    g_boff[256];
__device__ uint2  g_edge[EE];       // {src, __float_as_uint(0.9*w)}
__device__ uint4  g_h0h[NN * 8];    // fp16 h: 64 halves/row = 8 uint4
__device__ uint4  g_hah[NN * 8];
__device__ uint4  g_hbh[NN * 8];
__device__ __half g_Mh[NLAYERS * HID_ * HID_];
__device__ __half g_W1h[DIN_ * HID_];

// ---------------- helpers ---------------------------------------------------
__device__ __forceinline__ void fma8(float* acc, uint4 u, float w) {
    float2 p;
    p = __half22float2(*(__half2*)&u.x); acc[0] += w * p.x; acc[1] += w * p.y;
    p = __half22float2(*(__half2*)&u.y); acc[2] += w * p.x; acc[3] += w * p.y;
    p = __half22float2(*(__half2*)&u.z); acc[4] += w * p.x; acc[5] += w * p.y;
    p = __half22float2(*(__half2*)&u.w); acc[6] += w * p.x; acc[7] += w * p.y;
}

__device__ __forceinline__ void ldsm_x4(unsigned* r, unsigned addr) {
    asm volatile("ldmatrix.sync.aligned.m8n8.x4.shared.b16 {%0,%1,%2,%3}, [%4];"
                 : "=r"(r[0]), "=r"(r[1]), "=r"(r[2]), "=r"(r[3]) : "r"(addr));
}
__device__ __forceinline__ void ldsm_x4_t(unsigned* r, unsigned addr) {
    asm volatile("ldmatrix.sync.aligned.m8n8.x4.trans.shared.b16 {%0,%1,%2,%3}, [%4];"
                 : "=r"(r[0]), "=r"(r[1]), "=r"(r[2]), "=r"(r[3]) : "r"(addr));
}
__device__ __forceinline__ void mma_f16(float* d, const unsigned* a, const unsigned* b) {
    asm volatile(
        "mma.sync.aligned.m16n8k16.row.col.f32.f16.f16.f32 "
        "{%0,%1,%2,%3}, {%4,%5,%6,%7}, {%8,%9}, {%0,%1,%2,%3};"
        : "+f"(d[0]), "+f"(d[1]), "+f"(d[2]), "+f"(d[3])
        : "r"(a[0]), "r"(a[1]), "r"(a[2]), "r"(a[3]), "r"(b[0]), "r"(b[1]));
}

// ---------------- graph prep (edge_index is INT32) -------------------------
__global__ void deg_zero_k() {
    int i = blockIdx.x * blockDim.x + threadIdx.x;
    if (i < NN) g_degi[i] = 0;
}

__global__ void deg_count_k(const int* __restrict__ ei) {
    int e = blockIdx.x * blockDim.x + threadIdx.x;
    if (e < EE) {
        int d = ei[EE + e];
        if (d >= 0 && d < NN) atomicAdd(&g_degi[d], 1);
    }
}

// scan1 also computes dinv (reads g_degi anyway)
__global__ void scan1_k() {
    __shared__ int s[1024];
    int t = threadIdx.x;
    int i = blockIdx.x * 512 + t;
    int v = (i < NN) ? g_degi[i] : 0;
    if (i < NN) g_dinv[i] = rsqrtf((float)v + 1.0f);   // +1 self-loop
    s[t] = 0;
    s[512 + t] = v;
    __syncthreads();
#pragma unroll
    for (int d = 1; d < 512; d <<= 1) {
        int u = s[512 + t - d];
        __syncthreads();
        s[512 + t] += u;
        __syncthreads();
    }
    if (i < NN) g_off[i] = s[512 + t] - v;
    if (t == 511) g_bsum[blockIdx.x] = s[512 + 511];
}

__global__ void scan2_k() {
    __shared__ int s[512];
    int t = threadIdx.x;
    int v = (t < NB1) ? g_bsum[t] : 0;
    s[t] = 0;
    s[256 + t] = v;
    __syncthreads();
#pragma unroll
    for (int d = 1; d < 256; d <<= 1) {
        int u = s[256 + t - d];
        __syncthreads();
        s[256 + t] += u;
        __syncthreads();
    }
    g_boff[t] = s[256 + t] - v;
}

__global__ void scan3_k() {
    int i = blockIdx.x * 512 + threadIdx.x;
    if (i < NN) {
        int o = g_off[i] + g_boff[blockIdx.x];
        g_off[i] = o;
        g_cur[i] = o;
    }
}

__global__ void fill_k(const int* __restrict__ ei) {
    int e = blockIdx.x * blockDim.x + threadIdx.x;
    if (e < EE) {
        int s = ei[e];
        int d = ei[EE + e];
        if (s >= 0 && s < NN && d >= 0 && d < NN) {
            int pos = atomicAdd(&g_cur[d], 1);
            uint2 pe;
            pe.x = (unsigned)s;
            pe.y = __float_as_uint(0.9f * g_dinv[s] * g_dinv[d]);
            g_edge[pos] = pe;
        }
    }
}

// merged: M_l = (1-beta)*I + beta*W_l (fp16) AND W1 -> fp16
__global__ void weights_k(const float* __restrict__ cw, const float* __restrict__ W1) {
    int idx = blockIdx.x * blockDim.x + threadIdx.x;
    if (idx < NLAYERS * HID_ * HID_) {
        int l = idx >> 12;
        int rc = idx & 4095;
        int r = rc >> 6, c = rc & 63;
        float beta = logf(0.5f / (float)(l + 1) + 1.0f);
        float v = beta * cw[idx];
        if (r == c) v += 1.0f - beta;
        g_Mh[idx] = __float2half(v);
    } else if (idx < NLAYERS * HID_ * HID_ + DIN_ * HID_) {
        int k = idx - NLAYERS * HID_ * HID_;
        g_W1h[k] = __float2half(W1[k]);
    }
}

// ---------------- fused layer (R10 gather, 64-reg cap for 4 blocks/SM) -----
// 256 threads; 8 lanes/row (uint4 feature slice), 32 rows/pass, 2 passes.
__global__ void __launch_bounds__(256, 4) layer_k(int layer) {
    __shared__ __align__(16) __half Ah[64 * 72];   // row-major, stride 72 halves
    __shared__ __align__(16) __half Bh[64 * 72];

    const uint4* __restrict__ hin =
        (layer == 0) ? g_h0h : ((layer & 1) ? g_hah : g_hbh);
    uint4* __restrict__ hout = (layer & 1) ? g_hbh : g_hah;

    int tid = threadIdx.x;
    int row0 = blockIdx.x << 6;

    // load M_l (fp16) into Bh with padded stride
    {
        const unsigned* Mw = (const unsigned*)(g_Mh + layer * 4096);  // 2048 words
        unsigned* Bw = (unsigned*)Bh;
#pragma unroll
        for (int t = 0; t < 8; t++) {
            int v = t * 256 + tid;
            Bw[(v >> 5) * 36 + (v & 31)] = Mw[v];
        }
    }

    // gather: 8 lanes/row, uint4 (16B) per lane; 2 passes of 32 rows
    int j = tid & 7;
    int rbase = tid >> 3;
#pragma unroll
    for (int p = 0; p < 2; p++) {
        int rl = p * 32 + rbase;
        int row = row0 + rl;
        float acc[8] = {0.f, 0.f, 0.f, 0.f, 0.f, 0.f, 0.f, 0.f};
        if (row < NN) {
            float di = g_dinv[row];
            fma8(acc, hin[row * 8 + j], 0.9f * di * di);

            int beg = g_off[row];
            int deg = g_degi[row];
            const uint2* ep = g_edge + beg;
            int e = 0;
            for (; e + 3 < deg; e += 4) {
                uint2 q0 = ep[e], q1 = ep[e + 1], q2 = ep[e + 2], q3 = ep[e + 3];
                uint4 v0 = hin[q0.x * 8 + j];
                uint4 v1 = hin[q1.x * 8 + j];
                uint4 v2 = hin[q2.x * 8 + j];
                uint4 v3 = hin[q3.x * 8 + j];
                fma8(acc, v0, __uint_as_float(q0.y));
                fma8(acc, v1, __uint_as_float(q1.y));
                fma8(acc, v2, __uint_as_float(q2.y));
                fma8(acc, v3, __uint_as_float(q3.y));
            }
            for (; e + 1 < deg; e += 2) {
                uint2 q0 = ep[e], q1 = ep[e + 1];
                uint4 v0 = hin[q0.x * 8 + j];
                uint4 v1 = hin[q1.x * 8 + j];
                fma8(acc, v0, __uint_as_float(q0.y));
                fma8(acc, v1, __uint_as_float(q1.y));
            }
            if (e < deg) {
                uint2 q0 = ep[e];
                fma8(acc, hin[q0.x * 8 + j], __uint_as_float(q0.y));
            }
            fma8(acc, g_h0h[row * 8 + j], 0.1f);
        }
        __half2 p0 = __floats2half2_rn(acc[0], acc[1]);
        __half2 p1 = __floats2half2_rn(acc[2], acc[3]);
        __half2 p2 = __floats2half2_rn(acc[4], acc[5]);
        __half2 p3 = __floats2half2_rn(acc[6], acc[7]);
        uint4 st;
        st.x = *(unsigned*)&p0; st.y = *(unsigned*)&p1;
        st.z = *(unsigned*)&p2; st.w = *(unsigned*)&p3;
        *(uint4*)(Ah + rl * 72 + j * 8) = st;
    }
    __syncthreads();

    // HMMA: 8 warps, each 16x32 tile
    int w = tid >> 5, lane = tid & 31;
    int r0 = (w & 3) * 16;
    int n0 = (w >> 2) * 32;
    float d0[4] = {}, d1[4] = {}, d2[4] = {}, d3[4] = {};

    unsigned Asm = (unsigned)__cvta_generic_to_shared(Ah);
    unsigned Bsm = (unsigned)__cvta_generic_to_shared(Bh);
    int lr = lane & 15, lh = lane >> 4;
#pragma unroll
    for (int ks = 0; ks < 4; ks++) {
        int kk = ks * 16;
        unsigned a[4], b0[4], b1[4];
        ldsm_x4(a, Asm + ((r0 + lr) * 72 + kk + lh * 8) * 2);
        unsigned bad = Bsm + ((kk + lr) * 72 + n0 + lh * 8) * 2;
        ldsm_x4_t(b0, bad);
        ldsm_x4_t(b1, bad + 32);
        mma_f16(d0, a, b0 + 0);
        mma_f16(d1, a, b0 + 2);
        mma_f16(d2, a, b1 + 0);
        mma_f16(d3, a, b1 + 2);
    }

    // epilogue: relu, pack fp16, store
    int tg = lane >> 2, ti = lane & 3;
    unsigned* ho = (unsigned*)hout;   // 32 words per row
    int grow0 = row0 + r0 + tg;
    int grow1 = grow0 + 8;
    float* dd[4] = {d0, d1, d2, d3};
#pragma unroll
    for (int t = 0; t < 4; t++) {
        int col = n0 + t * 8 + ti * 2;
        __half2 lo = __floats2half2_rn(fmaxf(dd[t][0], 0.f), fmaxf(dd[t][1], 0.f));
        __half2 hi = __floats2half2_rn(fmaxf(dd[t][2], 0.f), fmaxf(dd[t][3], 0.f));
        if (grow0 < NN) ho[grow0 * 32 + (col >> 1)] = *(unsigned*)&lo;
        if (grow1 < NN) ho[grow1 * 32 + (col >> 1)] = *(unsigned*)&hi;
    }
}

// ---------------- GEMM1: h0 = relu(x @ W1 + b1), HMMA, K=128 ---------------
__global__ void __launch_bounds__(256) gemm1_k(
    const float* __restrict__ x, const float* __restrict__ bias)
{
    __shared__ __align__(16) __half Ah[64 * 72];
    __shared__ __align__(16) __half Bh[64 * 72];
    __shared__ float bsh[64];

    int tid = threadIdx.x;
    int row0 = blockIdx.x << 6;
    if (tid < 64) bsh[tid] = bias[tid];

    int w = tid >> 5, lane = tid & 31;
    int r0 = (w & 3) * 16;
    int n0 = (w >> 2) * 32;
    int lr = lane & 15, lh = lane >> 4;
    float d0[4] = {}, d1[4] = {}, d2[4] = {}, d3[4] = {};

    unsigned Asm = (unsigned)__cvta_generic_to_shared(Ah);
    unsigned Bsm = (unsigned)__cvta_generic_to_shared(Bh);

#pragma unroll
    for (int kc = 0; kc < 128; kc += 64) {
        {
            const unsigned* Ww = (const unsigned*)(g_W1h + kc * 64);
            unsigned* Bw = (unsigned*)Bh;
#pragma unroll
            for (int t = 0; t < 8; t++) {
                int v = t * 256 + tid;
                Bw[(v >> 5) * 36 + (v & 31)] = Ww[v];
            }
        }
        {
            int r = tid >> 2, q = tid & 3;
            int grow = row0 + r;
            float4 f0 = make_float4(0, 0, 0, 0), f1 = f0, f2 = f0, f3 = f0;
            if (grow < NN) {
                const float4* xr = (const float4*)x + grow * 32 + (kc >> 2) + q * 4;
                f0 = xr[0]; f1 = xr[1]; f2 = xr[2]; f3 = xr[3];
            }
            __half2 h0_ = __floats2half2_rn(f0.x, f0.y);
            __half2 h1_ = __floats2half2_rn(f0.z, f0.w);
            __half2 h2_ = __floats2half2_rn(f1.x, f1.y);
            __half2 h3_ = __floats2half2_rn(f1.z, f1.w);
            __half2 h4_ = __floats2half2_rn(f2.x, f2.y);
            __half2 h5_ = __floats2half2_rn(f2.z, f2.w);
            __half2 h6_ = __floats2half2_rn(f3.x, f3.y);
            __half2 h7_ = __floats2half2_rn(f3.z, f3.w);
            uint4 s0, s1;
            s0.x = *(unsigned*)&h0_; s0.y = *(unsigned*)&h1_;
            s0.z = *(unsigned*)&h2_; s0.w = *(unsigned*)&h3_;
            s1.x = *(unsigned*)&h4_; s1.y = *(unsigned*)&h5_;
            s1.z = *(unsigned*)&h6_; s1.w = *(unsigned*)&h7_;
            *(uint4*)(Ah + r * 72 + q * 16) = s0;
            *(uint4*)(Ah + r * 72 + q * 16 + 8) = s1;
        }
        __syncthreads();

#pragma unroll
        for (int ks = 0; ks < 4; ks++) {
            int kk = ks * 16;
            unsigned a[4], b0[4], b1[4];
            ldsm_x4(a, Asm + ((r0 + lr) * 72 + kk + lh * 8) * 2);
            unsigned bad = Bsm + ((kk + lr) * 72 + n0 + lh * 8) * 2;
            ldsm_x4_t(b0, bad);
            ldsm_x4_t(b1, bad + 32);
            mma_f16(d0, a, b0 + 0);
            mma_f16(d1, a, b0 + 2);
            mma_f16(d2, a, b1 + 0);
            mma_f16(d3, a, b1 + 2);
        }
        __syncthreads();
    }

    int tg = lane >> 2, ti = lane & 3;
    unsigned* ho = (unsigned*)g_h0h;
    int grow0 = row0 + r0 + tg;
    int grow1 = grow0 + 8;
    float* dd[4] = {d0, d1, d2, d3};
#pragma unroll
    for (int t = 0; t < 4; t++) {
        int col = n0 + t * 8 + ti * 2;
        float bx = bsh[col], by = bsh[col + 1];
        __half2 lo = __floats2half2_rn(fmaxf(dd[t][0] + bx, 0.f), fmaxf(dd[t][1] + by, 0.f));
        __half2 hi = __floats2half2_rn(fmaxf(dd[t][2] + bx, 0.f), fmaxf(dd[t][3] + by, 0.f));
        if (grow0 < NN) ho[grow0 * 32 + (col >> 1)] = *(unsigned*)&lo;
        if (grow1 < NN) ho[grow1 * 32 + (col >> 1)] = *(unsigned*)&hi;
    }
}

// ---------------- final GEMM: out = h @ W2 + b2  ([N,64]@[64,40]) ----------
__device__ __forceinline__ float4 u2f4(uint2 u) {
    __half2 a = *(__half2*)&u.x;
    __half2 b = *(__half2*)&u.y;
    float2 fa = __half22float2(a), fb = __half22float2(b);
    return make_float4(fa.x, fa.y, fb.x, fb.y);
}

__global__ void __launch_bounds__(256) final_k(
    const float* __restrict__ W2, const float* __restrict__ b2,
    float* __restrict__ out)
{
    __shared__ float W2s[64 * 40];
    __shared__ float b2s[40];
    int tid = threadIdx.x;
    for (int i = tid; i < 64 * 40; i += 256) W2s[i] = W2[i];
    if (tid < 40) b2s[tid] = b2[tid];
    __syncthreads();

    int row = blockIdx.x * 256 + tid;
    if (row >= NN) return;

    float acc[40];
#pragma unroll
    for (int j = 0; j < 40; j++) acc[j] = b2s[j];

    // last layer is 7 (odd) -> wrote g_hbh
    const uint4* hr = g_hbh + row * 8;
#pragma unroll
    for (int q = 0; q < 8; q++) {
        uint4 u = hr[q];
        float4 f0 = u2f4(make_uint2(u.x, u.y));
        float4 f1 = u2f4(make_uint2(u.z, u.w));
        float hs[8] = {f0.x, f0.y, f0.z, f0.w, f1.x, f1.y, f1.z, f1.w};
#pragma unroll
        for (int kk = 0; kk < 8; kk++) {
            const float* wrow = &W2s[(q * 8 + kk) * 40];
#pragma unroll
            for (int jj = 0; jj < 40; jj++)
                acc[jj] += hs[kk] * wrow[jj];
        }
    }
#pragma unroll
    for (int jj = 0; jj < 40; jj++)
        out[row * 40 + jj] = acc[jj];
}

// ---------------- launch ---------------------------------------------------
extern "C" void kernel_launch(void* const* d_in, const int* in_sizes, int n_in,
                              void* d_out, int out_size) {
    const float* x  = (const float*)d_in[0];
    const int*   ei = (const int*)d_in[1];     // int32 (jax default, no x64)
    const float* W1 = (const float*)d_in[2];
    const float* b1 = (const float*)d_in[3];
    const float* cw = (const float*)d_in[4];
    const float* W2 = (const float*)d_in[5];
    const float* b2 = (const float*)d_in[6];
    float*       out = (float*)d_out;

    deg_zero_k<<<(NN + 255) / 256, 256>>>();
    deg_count_k<<<(EE + 255) / 256, 256>>>(ei);
    scan1_k<<<NB1, 512>>>();
    scan2_k<<<1, 256>>>();
    scan3_k<<<NB1, 512>>>();
    fill_k<<<(EE + 255) / 256, 256>>>(ei);
    weights_k<<<(NLAYERS * HID_ * HID_ + DIN_ * HID_ + 255) / 256, 256>>>(cw, W1);

    gemm1_k<<<(NN + 63) / 64, 256>>>(x, b1);

    for (int l = 0; l < NLAYERS; l++)
        layer_k<<<(NN + 63) / 64, 256>>>(l);

    final_k<<<(NN + 255) / 256, 256>>>(W2, b2, out);
}

// round 17
// speedup vs baseline: 1.7225x; 1.1179x over previous
#include <cuda_runtime.h>
#include <cuda_fp16.h>
#include <math.h>

#define NN      100000
#define EE      1600000
#define DIN_    128
#define HID_    64
#define DOUT_   40
#define NLAYERS 8
#define NB1     ((NN + 511) / 512)   // 196 scan blocks

// ---------------- scratch (device globals; no allocation allowed) ----------
__device__ int    g_degi[NN];
__device__ float  g_dinv[NN];
__device__ int    g_off[NN + 1];
__device__ int    g_cur[NN];
__device__ int    g_bsum[256];
__device__ uint2  g_edge[EE];       // {src, __float_as_uint(0.9*w)}
__device__ uint4  g_h0h[NN * 8];    // fp16 h: 64 halves/row = 8 uint4
__device__ uint4  g_hah[NN * 8];
__device__ uint4  g_hbh[NN * 8];
__device__ __half g_Mh[NLAYERS * HID_ * HID_];
__device__ __half g_W2h[HID_ * DOUT_];

// ---------------- helpers ---------------------------------------------------
__device__ __forceinline__ void fma8(float* acc, uint4 u, float w) {
    float2 p;
    p = __half22float2(*(__half2*)&u.x); acc[0] += w * p.x; acc[1] += w * p.y;
    p = __half22float2(*(__half2*)&u.y); acc[2] += w * p.x; acc[3] += w * p.y;
    p = __half22float2(*(__half2*)&u.z); acc[4] += w * p.x; acc[5] += w * p.y;
    p = __half22float2(*(__half2*)&u.w); acc[6] += w * p.x; acc[7] += w * p.y;
}

__device__ __forceinline__ void ldsm_x4(unsigned* r, unsigned addr) {
    asm volatile("ldmatrix.sync.aligned.m8n8.x4.shared.b16 {%0,%1,%2,%3}, [%4];"
                 : "=r"(r[0]), "=r"(r[1]), "=r"(r[2]), "=r"(r[3]) : "r"(addr));
}
__device__ __forceinline__ void ldsm_x4_t(unsigned* r, unsigned addr) {
    asm volatile("ldmatrix.sync.aligned.m8n8.x4.trans.shared.b16 {%0,%1,%2,%3}, [%4];"
                 : "=r"(r[0]), "=r"(r[1]), "=r"(r[2]), "=r"(r[3]) : "r"(addr));
}
__device__ __forceinline__ void mma_f16(float* d, const unsigned* a, const unsigned* b) {
    asm volatile(
        "mma.sync.aligned.m16n8k16.row.col.f32.f16.f16.f32 "
        "{%0,%1,%2,%3}, {%4,%5,%6,%7}, {%8,%9}, {%0,%1,%2,%3};"
        : "+f"(d[0]), "+f"(d[1]), "+f"(d[2]), "+f"(d[3])
        : "r"(a[0]), "r"(a[1]), "r"(a[2]), "r"(a[3]), "r"(b[0]), "r"(b[1]));
}

// ---------------- graph prep (edge_index is INT32) -------------------------
__global__ void deg_zero_k() {
    int i = blockIdx.x * blockDim.x + threadIdx.x;
    if (i < NN) g_degi[i] = 0;
}

__global__ void deg_count_k(const int* __restrict__ ei) {
    int e = blockIdx.x * blockDim.x + threadIdx.x;
    if (e < EE) {
        int d = ei[EE + e];
        if (d >= 0 && d < NN) atomicAdd(&g_degi[d], 1);
    }
}

// scan1 also computes dinv (reads g_degi anyway)
__global__ void scan1_k() {
    __shared__ int s[1024];
    int t = threadIdx.x;
    int i = blockIdx.x * 512 + t;
    int v = (i < NN) ? g_degi[i] : 0;
    if (i < NN) g_dinv[i] = rsqrtf((float)v + 1.0f);   // +1 self-loop
    s[t] = 0;
    s[512 + t] = v;
    __syncthreads();
#pragma unroll
    for (int d = 1; d < 512; d <<= 1) {
        int u = s[512 + t - d];
        __syncthreads();
        s[512 + t] += u;
        __syncthreads();
    }
    if (i < NN) g_off[i] = s[512 + t] - v;
    if (t == 511) g_bsum[blockIdx.x] = s[512 + 511];
}

// scan3: each block re-reduces g_bsum[0..bid) in parallel (scan2 eliminated)
__global__ void scan3_k() {
    __shared__ int red[512];
    int t = threadIdx.x;
    int partial = 0;
    for (int k = t; k < blockIdx.x; k += 512) partial += g_bsum[k];
    red[t] = partial;
    __syncthreads();
#pragma unroll
    for (int d = 256; d > 0; d >>= 1) {
        if (t < d) red[t] += red[t + d];
        __syncthreads();
    }
    int boff = red[0];
    int i = blockIdx.x * 512 + t;
    if (i < NN) {
        int o = g_off[i] + boff;
        g_off[i] = o;
        g_cur[i] = o;
    }
}

__global__ void fill_k(const int* __restrict__ ei) {
    int e = blockIdx.x * blockDim.x + threadIdx.x;
    if (e < EE) {
        int s = ei[e];
        int d = ei[EE + e];
        if (s >= 0 && s < NN && d >= 0 && d < NN) {
            int pos = atomicAdd(&g_cur[d], 1);
            uint2 pe;
            pe.x = (unsigned)s;
            pe.y = __float_as_uint(0.9f * g_dinv[s] * g_dinv[d]);
            g_edge[pos] = pe;
        }
    }
}

// M_l = (1-beta)*I + beta*W_l (fp16) AND W2 -> fp16
__global__ void weights_k(const float* __restrict__ cw, const float* __restrict__ W2) {
    int idx = blockIdx.x * blockDim.x + threadIdx.x;
    if (idx < NLAYERS * HID_ * HID_) {
        int l = idx >> 12;
        int rc = idx & 4095;
        int r = rc >> 6, c = rc & 63;
        float beta = logf(0.5f / (float)(l + 1) + 1.0f);
        float v = beta * cw[idx];
        if (r == c) v += 1.0f - beta;
        g_Mh[idx] = __float2half(v);
    } else if (idx < NLAYERS * HID_ * HID_ + HID_ * DOUT_) {
        int k = idx - NLAYERS * HID_ * HID_;
        g_W2h[k] = __float2half(W2[k]);
    }
}

// ---------------- fused layer: gather + HMMA (+ optional final GEMM) -------
// 256 threads; 8 lanes/row (uint4 feature slice), 32 rows/pass, 2 passes.
template <bool FINAL>
__global__ void __launch_bounds__(256, 4) layer_k(int layer, const float* __restrict__ b2,
                                                  float* __restrict__ out) {
    __shared__ __align__(16) __half Ah[64 * 72];   // row-major, stride 72 halves
    __shared__ __align__(16) __half Bh[64 * 72];
    __shared__ float b2s[40];

    const uint4* __restrict__ hin =
        (layer == 0) ? g_h0h : ((layer & 1) ? g_hah : g_hbh);
    uint4* __restrict__ hout = (layer & 1) ? g_hbh : g_hah;

    int tid = threadIdx.x;
    int row0 = blockIdx.x << 6;

    if (FINAL && tid < 40) b2s[tid] = b2[tid];

    // load M_l (fp16) into Bh with padded stride
    {
        const unsigned* Mw = (const unsigned*)(g_Mh + layer * 4096);  // 2048 words
        unsigned* Bw = (unsigned*)Bh;
#pragma unroll
        for (int t = 0; t < 8; t++) {
            int v = t * 256 + tid;
            Bw[(v >> 5) * 36 + (v & 31)] = Mw[v];
        }
    }

    // gather: 8 lanes/row, uint4 (16B) per lane; 2 passes of 32 rows
    int j = tid & 7;
    int rbase = tid >> 3;
#pragma unroll
    for (int p = 0; p < 2; p++) {
        int rl = p * 32 + rbase;
        int row = row0 + rl;
        float acc[8] = {0.f, 0.f, 0.f, 0.f, 0.f, 0.f, 0.f, 0.f};
        if (row < NN) {
            float di = g_dinv[row];
            fma8(acc, hin[row * 8 + j], 0.9f * di * di);

            int beg = g_off[row];
            int deg = g_degi[row];
            const uint2* ep = g_edge + beg;
            int e = 0;
            for (; e + 3 < deg; e += 4) {
                uint2 q0 = ep[e], q1 = ep[e + 1], q2 = ep[e + 2], q3 = ep[e + 3];
                uint4 v0 = hin[q0.x * 8 + j];
                uint4 v1 = hin[q1.x * 8 + j];
                uint4 v2 = hin[q2.x * 8 + j];
                uint4 v3 = hin[q3.x * 8 + j];
                fma8(acc, v0, __uint_as_float(q0.y));
                fma8(acc, v1, __uint_as_float(q1.y));
                fma8(acc, v2, __uint_as_float(q2.y));
                fma8(acc, v3, __uint_as_float(q3.y));
            }
            for (; e + 1 < deg; e += 2) {
                uint2 q0 = ep[e], q1 = ep[e + 1];
                uint4 v0 = hin[q0.x * 8 + j];
                uint4 v1 = hin[q1.x * 8 + j];
                fma8(acc, v0, __uint_as_float(q0.y));
                fma8(acc, v1, __uint_as_float(q1.y));
            }
            if (e < deg) {
                uint2 q0 = ep[e];
                fma8(acc, hin[q0.x * 8 + j], __uint_as_float(q0.y));
            }
            fma8(acc, g_h0h[row * 8 + j], 0.1f);
        }
        __half2 p0 = __floats2half2_rn(acc[0], acc[1]);
        __half2 p1 = __floats2half2_rn(acc[2], acc[3]);
        __half2 p2 = __floats2half2_rn(acc[4], acc[5]);
        __half2 p3 = __floats2half2_rn(acc[6], acc[7]);
        uint4 st;
        st.x = *(unsigned*)&p0; st.y = *(unsigned*)&p1;
        st.z = *(unsigned*)&p2; st.w = *(unsigned*)&p3;
        *(uint4*)(Ah + rl * 72 + j * 8) = st;
    }
    __syncthreads();

    // HMMA: 8 warps, each 16x32 tile
    int w = tid >> 5, lane = tid & 31;
    int r0 = (w & 3) * 16;
    int n0 = (w >> 2) * 32;
    float d0[4] = {}, d1[4] = {}, d2[4] = {}, d3[4] = {};

    unsigned Asm = (unsigned)__cvta_generic_to_shared(Ah);
    unsigned Bsm = (unsigned)__cvta_generic_to_shared(Bh);
    int lr = lane & 15, lh = lane >> 4;
#pragma unroll
    for (int ks = 0; ks < 4; ks++) {
        int kk = ks * 16;
        unsigned a[4], b0[4], b1[4];
        ldsm_x4(a, Asm + ((r0 + lr) * 72 + kk + lh * 8) * 2);
        unsigned bad = Bsm + ((kk + lr) * 72 + n0 + lh * 8) * 2;
        ldsm_x4_t(b0, bad);
        ldsm_x4_t(b1, bad + 32);
        mma_f16(d0, a, b0 + 0);
        mma_f16(d1, a, b0 + 2);
        mma_f16(d2, a, b1 + 0);
        mma_f16(d3, a, b1 + 2);
    }

    int tg = lane >> 2, ti = lane & 3;
    float* dd[4] = {d0, d1, d2, d3};

    if (!FINAL) {
        // epilogue: relu, pack fp16, store h
        unsigned* ho = (unsigned*)hout;   // 32 words per row
        int grow0 = row0 + r0 + tg;
        int grow1 = grow0 + 8;
#pragma unroll
        for (int t = 0; t < 4; t++) {
            int col = n0 + t * 8 + ti * 2;
            __half2 lo = __floats2half2_rn(fmaxf(dd[t][0], 0.f), fmaxf(dd[t][1], 0.f));
            __half2 hi = __floats2half2_rn(fmaxf(dd[t][2], 0.f), fmaxf(dd[t][3], 0.f));
            if (grow0 < NN) ho[grow0 * 32 + (col >> 1)] = *(unsigned*)&lo;
            if (grow1 < NN) ho[grow1 * 32 + (col >> 1)] = *(unsigned*)&hi;
        }
    } else {
        // FINAL: relu + repack into Ah, then out = Ah @ W2 + b2
        __syncthreads();   // all warps done reading Ah
        int rl0 = r0 + tg, rl1 = rl0 + 8;
#pragma unroll
        for (int t = 0; t < 4; t++) {
            int col = n0 + t * 8 + ti * 2;
            __half2 lo = __floats2half2_rn(fmaxf(dd[t][0], 0.f), fmaxf(dd[t][1], 0.f));
            __half2 hi = __floats2half2_rn(fmaxf(dd[t][2], 0.f), fmaxf(dd[t][3], 0.f));
            *(__half2*)(Ah + rl0 * 72 + col) = lo;
            *(__half2*)(Ah + rl1 * 72 + col) = hi;
        }
        // rebuild Bh = W2 (64x40 fp16, zero-padded to 64x64), padded stride
        {
            unsigned* Bw = (unsigned*)Bh;
#pragma unroll
            for (int t = 0; t < 8; t++) {
                int v = t * 256 + tid;       // word 0..2047
                int r = v >> 5;
                int c = (v & 31) * 2;
                unsigned word = 0;
                if (c < 40) {
                    __half a = g_W2h[r * 40 + c];
                    __half b = (c + 1 < 40) ? g_W2h[r * 40 + c + 1] : __float2half(0.f);
                    __half2 h2 = __halves2half2(a, b);
                    word = *(unsigned*)&h2;
                }
                Bw[r * 36 + (v & 31)] = word;
            }
        }
        __syncthreads();

        float e0[4] = {}, e1[4] = {}, e2[4] = {}, e3[4] = {};
#pragma unroll
        for (int ks = 0; ks < 4; ks++) {
            int kk = ks * 16;
            unsigned a[4], b0[4], b1[4];
            ldsm_x4(a, Asm + ((r0 + lr) * 72 + kk + lh * 8) * 2);
            unsigned bad = Bsm + ((kk + lr) * 72 + n0 + lh * 8) * 2;
            ldsm_x4_t(b0, bad);
            ldsm_x4_t(b1, bad + 32);
            mma_f16(e0, a, b0 + 0);
            mma_f16(e1, a, b0 + 2);
            mma_f16(e2, a, b1 + 0);
            mma_f16(e3, a, b1 + 2);
        }
        float* ee[4] = {e0, e1, e2, e3};
        int grow0 = row0 + r0 + tg;
        int grow1 = grow0 + 8;
#pragma unroll
        for (int t = 0; t < 4; t++) {
            int col = n0 + t * 8 + ti * 2;
            if (col < 40) {
                float bx = b2s[col], by = b2s[col + 1];
                if (grow0 < NN) {
                    out[grow0 * 40 + col]     = ee[t][0] + bx;
                    out[grow0 * 40 + col + 1] = ee[t][1] + by;
                }
                if (grow1 < NN) {
                    out[grow1 * 40 + col]     = ee[t][2] + bx;
                    out[grow1 * 40 + col + 1] = ee[t][3] + by;
                }
            }
        }
    }
}

// ---------------- GEMM1: h0 = relu(x @ W1 + b1), HMMA, K=128 ---------------
// W1 converted fp32->fp16 inline while staging Bh.
__global__ void __launch_bounds__(256) gemm1_k(
    const float* __restrict__ x, const float* __restrict__ W1,
    const float* __restrict__ bias)
{
    __shared__ __align__(16) __half Ah[64 * 72];
    __shared__ __align__(16) __half Bh[64 * 72];
    __shared__ float bsh[64];

    int tid = threadIdx.x;
    int row0 = blockIdx.x << 6;
    if (tid < 64) bsh[tid] = bias[tid];

    int w = tid >> 5, lane = tid & 31;
    int r0 = (w & 3) * 16;
    int n0 = (w >> 2) * 32;
    int lr = lane & 15, lh = lane >> 4;
    float d0[4] = {}, d1[4] = {}, d2[4] = {}, d3[4] = {};

    unsigned Asm = (unsigned)__cvta_generic_to_shared(Ah);
    unsigned Bsm = (unsigned)__cvta_generic_to_shared(Bh);

#pragma unroll
    for (int kc = 0; kc < 128; kc += 64) {
        // W1 chunk rows kc..kc+63 fp32 -> fp16 Bh (padded stride)
        {
            unsigned* Bw = (unsigned*)Bh;
            const float* Wc = W1 + kc * 64;
#pragma unroll
            for (int t = 0; t < 8; t++) {
                int v = t * 256 + tid;       // word 0..2047
                int r = v >> 5;
                int c = (v & 31) * 2;
                float2 f = *(const float2*)(Wc + r * 64 + c);
                __half2 h2 = __floats2half2_rn(f.x, f.y);
                Bw[r * 36 + (v & 31)] = *(unsigned*)&h2;
            }
        }
        // x chunk [64 rows x 64 cols fp32] -> fp16 Ah
        {
            int r = tid >> 2, q = tid & 3;
            int grow = row0 + r;
            float4 f0 = make_float4(0, 0, 0, 0), f1 = f0, f2 = f0, f3 = f0;
            if (grow < NN) {
                const float4* xr = (const float4*)x + grow * 32 + (kc >> 2) + q * 4;
                f0 = xr[0]; f1 = xr[1]; f2 = xr[2]; f3 = xr[3];
            }
            __half2 h0_ = __floats2half2_rn(f0.x, f0.y);
            __half2 h1_ = __floats2half2_rn(f0.z, f0.w);
            __half2 h2_ = __floats2half2_rn(f1.x, f1.y);
            __half2 h3_ = __floats2half2_rn(f1.z, f1.w);
            __half2 h4_ = __floats2half2_rn(f2.x, f2.y);
            __half2 h5_ = __floats2half2_rn(f2.z, f2.w);
            __half2 h6_ = __floats2half2_rn(f3.x, f3.y);
            __half2 h7_ = __floats2half2_rn(f3.z, f3.w);
            uint4 s0, s1;
            s0.x = *(unsigned*)&h0_; s0.y = *(unsigned*)&h1_;
            s0.z = *(unsigned*)&h2_; s0.w = *(unsigned*)&h3_;
            s1.x = *(unsigned*)&h4_; s1.y = *(unsigned*)&h5_;
            s1.z = *(unsigned*)&h6_; s1.w = *(unsigned*)&h7_;
            *(uint4*)(Ah + r * 72 + q * 16) = s0;
            *(uint4*)(Ah + r * 72 + q * 16 + 8) = s1;
        }
        __syncthreads();

#pragma unroll
        for (int ks = 0; ks < 4; ks++) {
            int kk = ks * 16;
            unsigned a[4], b0[4], b1[4];
            ldsm_x4(a, Asm + ((r0 + lr) * 72 + kk + lh * 8) * 2);
            unsigned bad = Bsm + ((kk + lr) * 72 + n0 + lh * 8) * 2;
            ldsm_x4_t(b0, bad);
            ldsm_x4_t(b1, bad + 32);
            mma_f16(d0, a, b0 + 0);
            mma_f16(d1, a, b0 + 2);
            mma_f16(d2, a, b1 + 0);
            mma_f16(d3, a, b1 + 2);
        }
        __syncthreads();
    }

    int tg = lane >> 2, ti = lane & 3;
    unsigned* ho = (unsigned*)g_h0h;
    int grow0 = row0 + r0 + tg;
    int grow1 = grow0 + 8;
    float* dd[4] = {d0, d1, d2, d3};
#pragma unroll
    for (int t = 0; t < 4; t++) {
        int col = n0 + t * 8 + ti * 2;
        float bx = bsh[col], by = bsh[col + 1];
        __half2 lo = __floats2half2_rn(fmaxf(dd[t][0] + bx, 0.f), fmaxf(dd[t][1] + by, 0.f));
        __half2 hi = __floats2half2_rn(fmaxf(dd[t][2] + bx, 0.f), fmaxf(dd[t][3] + by, 0.f));
        if (grow0 < NN) ho[grow0 * 32 + (col >> 1)] = *(unsigned*)&lo;
        if (grow1 < NN) ho[grow1 * 32 + (col >> 1)] = *(unsigned*)&hi;
    }
}

// ---------------- launch ---------------------------------------------------
extern "C" void kernel_launch(void* const* d_in, const int* in_sizes, int n_in,
                              void* d_out, int out_size) {
    const float* x  = (const float*)d_in[0];
    const int*   ei = (const int*)d_in[1];     // int32 (jax default, no x64)
    const float* W1 = (const float*)d_in[2];
    const float* b1 = (const float*)d_in[3];
    const float* cw = (const float*)d_in[4];
    const float* W2 = (const float*)d_in[5];
    const float* b2 = (const float*)d_in[6];
    float*       out = (float*)d_out;

    deg_zero_k<<<(NN + 255) / 256, 256>>>();
    deg_count_k<<<(EE + 255) / 256, 256>>>(ei);
    scan1_k<<<NB1, 512>>>();
    scan3_k<<<NB1, 512>>>();
    fill_k<<<(EE + 255) / 256, 256>>>(ei);
    weights_k<<<(NLAYERS * HID_ * HID_ + HID_ * DOUT_ + 255) / 256, 256>>>(cw, W2);

    gemm1_k<<<(NN + 63) / 64, 256>>>(x, W1, b1);

    for (int l = 0; l < NLAYERS - 1; l++)
        layer_k<false><<<(NN + 63) / 64, 256>>>(l, nullptr, nullptr);
    layer_k<true><<<(NN + 63) / 64, 256>>>(NLAYERS - 1, b2, out);
}